// round 1
// baseline (speedup 1.0000x reference)
#include <cuda_runtime.h>
#include <cuda_bf16.h>

// Problem constants
#define B_   4
#define S_   256
#define H_   768
#define C_   4      // NUM_BASIC
#define KTOT 3840   // 5*768 : 4 aggc slots + hidden copy (self-loop)

// Scratch (static __device__ allocations — no cudaMalloc allowed)
__device__ float g_W[B_ * C_ * S_ * S_];        // [B,4,S,S]  4 MB
__device__ float g_aggc[B_ * S_ * 5 * H_];      // [B,S,5,H] 15 MB (slot 4 = hidden copy)
__device__ float g_selfT[H_ * H_];              // self_weight transposed: [in,out]

// ---------------------------------------------------------------------------
// Kernel 1: per (b,i) — histogram relation labels, build dense weight matrix
// W[b,c,i,j], and copy hidden row into aggc slot 4.
// grid = B*S blocks, 256 threads.
// ---------------------------------------------------------------------------
__global__ void build_w_kernel(const float* __restrict__ hidden,
                               const int*   __restrict__ rels,
                               const float* __restrict__ rel_weight) {
    const int bi = blockIdx.x;
    const int b = bi >> 8;
    const int i = bi & 255;
    const int t = threadIdx.x;

    __shared__ int   cf[32], cr[32];
    __shared__ float inv_f[32], inv_r[32];
    __shared__ float rw[64 * 4];

    if (t < 32) { cf[t] = 0; cr[t] = 0; }
    rw[t] = rel_weight[t];           // 64*4 = 256 elems
    __syncthreads();

    const int lf = rels[(b * S_ + i) * S_ + t];   // rels[b,i,t]
    const int lr = rels[(b * S_ + t) * S_ + i];   // rels[b,t,i]
    if (lf > 0) atomicAdd(&cf[lf], 1);
    if (lr > 0) atomicAdd(&cr[lr], 1);
    __syncthreads();

    if (t < 32) {
        inv_f[t] = 1.0f / (float)(cf[t] > 0 ? cf[t] : 1);
        inv_r[t] = 1.0f / (float)(cr[t] > 0 ? cr[t] : 1);
    }
    __syncthreads();

    float w[4] = {0.f, 0.f, 0.f, 0.f};
    if (lf > 0) {
        const float s = inv_f[lf];
        #pragma unroll
        for (int c = 0; c < 4; c++) w[c] += rw[lf * 4 + c] * s;
    }
    if (lr > 0) {
        const float s = inv_r[lr];
        #pragma unroll
        for (int c = 0; c < 4; c++) w[c] += rw[(lr + 32) * 4 + c] * s;
    }
    #pragma unroll
    for (int c = 0; c < 4; c++)
        g_W[(((b * C_ + c) * S_) + i) * S_ + t] = w[c];

    // copy hidden[b,i,:] into aggc slot 4 (self-loop operand for kernel 3)
    const float* hrow = hidden + (size_t)(b * S_ + i) * H_;
    float* drow = g_aggc + ((size_t)(b * S_ + i) * 5 + 4) * H_;
    #pragma unroll
    for (int u = 0; u < 3; u++) drow[t + 256 * u] = hrow[t + 256 * u];
}

// ---------------------------------------------------------------------------
// Kernel 1b: transpose self_weight (out,in) -> g_selfT (in,out)
// ---------------------------------------------------------------------------
__global__ void transpose_self_kernel(const float* __restrict__ sw) {
    __shared__ float tile[32][33];
    const int x = blockIdx.x * 32 + threadIdx.x;  // in  (src col)
    const int y = blockIdx.y * 32 + threadIdx.y;  // out (src row)
    #pragma unroll
    for (int r = 0; r < 4; r++)
        tile[threadIdx.y + 8 * r][threadIdx.x] = sw[(y + 8 * r) * H_ + x];
    __syncthreads();
    const int x2 = blockIdx.y * 32 + threadIdx.x; // out (dst col)
    const int y2 = blockIdx.x * 32 + threadIdx.y; // in  (dst row)
    #pragma unroll
    for (int r = 0; r < 4; r++)
        g_selfT[(y2 + 8 * r) * H_ + x2] = tile[threadIdx.x][threadIdx.y + 8 * r];
}

// ---------------------------------------------------------------------------
// Kernel 2: batched GEMM  aggc[b,c] = W[b,c] (256x256) @ hidden[b] (256x768)
// 64x64 block tile, 256 threads, 4x4 micro-tile, K-tile 16.
// grid = (N/64=12, M/64=4, B*C=16)
// ---------------------------------------------------------------------------
__global__ __launch_bounds__(256) void gemm_agg_kernel(const float* __restrict__ hidden) {
    const int bc = blockIdx.z;
    const int b = bc >> 2, c = bc & 3;
    const float* __restrict__ A  = g_W + (size_t)bc * S_ * S_;          // [256,256]
    const float* __restrict__ Bm = hidden + (size_t)b * S_ * H_;        // [256,768]
    const int n0 = blockIdx.x * 64;
    const int m0 = blockIdx.y * 64;

    __shared__ float As[16][65];
    __shared__ float Bs[16][68];

    const int t = threadIdx.x;
    const int tx = t & 15, ty = t >> 4;

    float acc[4][4] = {};

    for (int k0 = 0; k0 < 256; k0 += 16) {
        #pragma unroll
        for (int u = 0; u < 4; u++) {
            const int idx = t + 256 * u;
            const int m = idx >> 4, kk = idx & 15;
            As[kk][m] = A[(m0 + m) * 256 + k0 + kk];
        }
        #pragma unroll
        for (int u = 0; u < 4; u++) {
            const int idx = t + 256 * u;
            const int kk = idx >> 6, nn = idx & 63;
            Bs[kk][nn] = Bm[(k0 + kk) * H_ + n0 + nn];
        }
        __syncthreads();
        #pragma unroll
        for (int kk = 0; kk < 16; kk++) {
            const float a0 = As[kk][ty * 4 + 0];
            const float a1 = As[kk][ty * 4 + 1];
            const float a2 = As[kk][ty * 4 + 2];
            const float a3 = As[kk][ty * 4 + 3];
            const float4 bv = *(const float4*)&Bs[kk][tx * 4];
            acc[0][0] += a0 * bv.x; acc[0][1] += a0 * bv.y; acc[0][2] += a0 * bv.z; acc[0][3] += a0 * bv.w;
            acc[1][0] += a1 * bv.x; acc[1][1] += a1 * bv.y; acc[1][2] += a1 * bv.z; acc[1][3] += a1 * bv.w;
            acc[2][0] += a2 * bv.x; acc[2][1] += a2 * bv.y; acc[2][2] += a2 * bv.z; acc[2][3] += a2 * bv.w;
            acc[3][0] += a3 * bv.x; acc[3][1] += a3 * bv.y; acc[3][2] += a3 * bv.z; acc[3][3] += a3 * bv.w;
        }
        __syncthreads();
    }

    #pragma unroll
    for (int r = 0; r < 4; r++) {
        const int i = m0 + ty * 4 + r;
        float* dst = g_aggc + (((size_t)(b * S_ + i) * 5) + c) * H_ + n0 + tx * 4;
        float4 v = make_float4(acc[r][0], acc[r][1], acc[r][2], acc[r][3]);
        *(float4*)dst = v;
    }
}

// ---------------------------------------------------------------------------
// Kernel 3: out[row, n] = Sum_k A[row, k] * Bop[k, n]
//   A   = g_aggc viewed as [1024, 3840]  (row = b*256+i, contiguous)
//   Bop = rows 0..3071: basic (already [3072,768] row-major)
//         rows 3072..3839: g_selfT  (self_weight^T)
// grid = (768/64=12, 1024/64=16), 256 threads, 64x64 tile, 4x4 micro.
// ---------------------------------------------------------------------------
__global__ __launch_bounds__(256) void gemm_out_kernel(const float* __restrict__ basic,
                                                       float* __restrict__ out) {
    const int n0 = blockIdx.x * 64;
    const int m0 = blockIdx.y * 64;

    __shared__ float As[16][65];
    __shared__ float Bs[16][68];

    const int t = threadIdx.x;
    const int tx = t & 15, ty = t >> 4;

    float acc[4][4] = {};

    for (int k0 = 0; k0 < KTOT; k0 += 16) {
        #pragma unroll
        for (int u = 0; u < 4; u++) {
            const int idx = t + 256 * u;
            const int m = idx >> 4, kk = idx & 15;
            As[kk][m] = g_aggc[(size_t)(m0 + m) * KTOT + k0 + kk];
        }
        const float* __restrict__ Bsrc =
            (k0 < 3072) ? (basic + (size_t)k0 * H_) : (g_selfT + (size_t)(k0 - 3072) * H_);
        #pragma unroll
        for (int u = 0; u < 4; u++) {
            const int idx = t + 256 * u;
            const int kk = idx >> 6, nn = idx & 63;
            Bs[kk][nn] = Bsrc[kk * H_ + n0 + nn];
        }
        __syncthreads();
        #pragma unroll
        for (int kk = 0; kk < 16; kk++) {
            const float a0 = As[kk][ty * 4 + 0];
            const float a1 = As[kk][ty * 4 + 1];
            const float a2 = As[kk][ty * 4 + 2];
            const float a3 = As[kk][ty * 4 + 3];
            const float4 bv = *(const float4*)&Bs[kk][tx * 4];
            acc[0][0] += a0 * bv.x; acc[0][1] += a0 * bv.y; acc[0][2] += a0 * bv.z; acc[0][3] += a0 * bv.w;
            acc[1][0] += a1 * bv.x; acc[1][1] += a1 * bv.y; acc[1][2] += a1 * bv.z; acc[1][3] += a1 * bv.w;
            acc[2][0] += a2 * bv.x; acc[2][1] += a2 * bv.y; acc[2][2] += a2 * bv.z; acc[2][3] += a2 * bv.w;
            acc[3][0] += a3 * bv.x; acc[3][1] += a3 * bv.y; acc[3][2] += a3 * bv.z; acc[3][3] += a3 * bv.w;
        }
        __syncthreads();
    }

    #pragma unroll
    for (int r = 0; r < 4; r++) {
        const int row = m0 + ty * 4 + r;
        float4 v = make_float4(acc[r][0], acc[r][1], acc[r][2], acc[r][3]);
        *(float4*)(out + (size_t)row * H_ + n0 + tx * 4) = v;
    }
}

// ---------------------------------------------------------------------------
extern "C" void kernel_launch(void* const* d_in, const int* in_sizes, int n_in,
                              void* d_out, int out_size) {
    const float* hidden     = (const float*)d_in[0]; // [4,256,768]
    const int*   rels       = (const int*)  d_in[1]; // [4,256,256]
    const float* basic      = (const float*)d_in[2]; // [4,768,768]
    const float* rel_weight = (const float*)d_in[3]; // [64,4]
    const float* self_w     = (const float*)d_in[4]; // [768,768] (out,in)
    float* out = (float*)d_out;                      // [4,256,768]

    build_w_kernel<<<B_ * S_, 256>>>(hidden, rels, rel_weight);
    transpose_self_kernel<<<dim3(H_ / 32, H_ / 32), dim3(32, 8)>>>(self_w);
    gemm_agg_kernel<<<dim3(H_ / 64, S_ / 64, B_ * C_), 256>>>(hidden);
    gemm_out_kernel<<<dim3(H_ / 64, (B_ * S_) / 64), 256>>>(basic, out);
}

// round 3
// speedup vs baseline: 1.9032x; 1.9032x over previous
#include <cuda_runtime.h>
#include <cuda_bf16.h>
#include <cstdint>

#define B_   4
#define S_   256
#define H_   768
#define KTOT 3840   // 5*768 : 4 aggc slots + hidden copy (self-loop)

// ---------------- static device scratch (no cudaMalloc allowed) -------------
__device__ __align__(256) __nv_bfloat16 g_Whi[16 * 256 * 256];
__device__ __align__(256) __nv_bfloat16 g_Wlo[16 * 256 * 256];
__device__ __align__(256) __nv_bfloat16 g_hThi[B_ * H_ * S_];    // [b,h,s]
__device__ __align__(256) __nv_bfloat16 g_hTlo[B_ * H_ * S_];
__device__ __align__(256) __nv_bfloat16 g_bThi[H_ * KTOT];       // [n,k] = Bop^T
__device__ __align__(256) __nv_bfloat16 g_bTlo[H_ * KTOT];
__device__ __align__(256) __nv_bfloat16 g_agghi[B_ * S_ * KTOT]; // [row,k]
__device__ __align__(256) __nv_bfloat16 g_agglo[B_ * S_ * KTOT];

// ---------------- helpers ---------------------------------------------------
__device__ __forceinline__ uint32_t s2u(const void* p) {
    uint32_t a;
    asm("{ .reg .u64 t; cvta.to.shared.u64 t, %1; cvt.u32.u64 %0, t; }"
        : "=r"(a) : "l"(p));
    return a;
}

__device__ __forceinline__ void cp16(uint32_t dst, const void* src) {
    asm volatile("cp.async.cg.shared.global [%0], [%1], 16;"
                 :: "r"(dst), "l"(src) : "memory");
}

__device__ __forceinline__ void ldsm4(uint32_t* r, uint32_t addr) {
    asm volatile("ldmatrix.sync.aligned.m8n8.x4.shared.b16 {%0,%1,%2,%3}, [%4];"
                 : "=r"(r[0]), "=r"(r[1]), "=r"(r[2]), "=r"(r[3]) : "r"(addr));
}

__device__ __forceinline__ void mma_bf16(float* d, const uint32_t* a,
                                         uint32_t b0, uint32_t b1) {
    asm volatile("mma.sync.aligned.m16n8k16.row.col.f32.bf16.bf16.f32 "
                 "{%0,%1,%2,%3}, {%4,%5,%6,%7}, {%8,%9}, {%0,%1,%2,%3};"
                 : "+f"(d[0]), "+f"(d[1]), "+f"(d[2]), "+f"(d[3])
                 : "r"(a[0]), "r"(a[1]), "r"(a[2]), "r"(a[3]), "r"(b0), "r"(b1));
}

__device__ __forceinline__ void split_bf16(float v, __nv_bfloat16& h, __nv_bfloat16& l) {
    h = __float2bfloat16_rn(v);
    l = __float2bfloat16_rn(v - __bfloat162float(h));
}

// ---------------- GEMM core -------------------------------------------------
// CTA tile 128x64, 8 warps (warp tile 32x32), K-chunk 16, double-buffered
// cp.async. SMEM rows: [hi 32B | lo 32B | pad 16B] -> pitch 80 (conflict-free
// ldmatrix: bank shift 20 words/row).
#define A_PITCH_BYTES (128 * 80)
#define B_PITCH_BYTES (64 * 80)

__device__ __forceinline__ void issue_chunk(
    const __nv_bfloat16* __restrict__ Ahi, const __nv_bfloat16* __restrict__ Alo, int lda,
    const __nv_bfloat16* __restrict__ Bhi, const __nv_bfloat16* __restrict__ Blo, int ldb,
    int m0, int n0, int k0, uint32_t a_s, uint32_t b_s, int t)
{
    #pragma unroll
    for (int u = 0; u < 2; u++) {
        const int id = t + 256 * u;
        const int r = id >> 2, q = id & 3;
        const __nv_bfloat16* sp = (q < 2) ? Ahi : Alo;
        cp16(a_s + r * 80 + (q & 1) * 16 + (q >> 1) * 32,
             sp + (size_t)(m0 + r) * lda + k0 + (q & 1) * 8);
    }
    {
        const int r = t >> 2, q = t & 3;
        const __nv_bfloat16* sp = (q < 2) ? Bhi : Blo;
        cp16(b_s + r * 80 + (q & 1) * 16 + (q >> 1) * 32,
             sp + (size_t)(n0 + r) * ldb + k0 + (q & 1) * 8);
    }
    asm volatile("cp.async.commit_group;" ::: "memory");
}

template<int NC>
__device__ __forceinline__ void gemm_core(
    const __nv_bfloat16* __restrict__ Ahi, const __nv_bfloat16* __restrict__ Alo, int lda,
    const __nv_bfloat16* __restrict__ Bhi, const __nv_bfloat16* __restrict__ Blo, int ldb,
    int m0, int n0, uint32_t asu, uint32_t bsu, float acc[2][4][4])
{
    const int t = threadIdx.x;
    const int lane = t & 31;
    const int wid = t >> 5;
    const int wm = wid & 3;
    const int wn = wid >> 2;

    issue_chunk(Ahi, Alo, lda, Bhi, Blo, ldb, m0, n0, 0, asu, bsu, t);

    const int arow = wm * 32 + (lane & 15);
    const int brow = wn * 32 + (lane & 15);
    const uint32_t koff = (uint32_t)(lane >> 4) * 16;

    for (int c = 0; c < NC; c++) {
        const int bufi = c & 1;
        if (c + 1 < NC) {
            issue_chunk(Ahi, Alo, lda, Bhi, Blo, ldb, m0, n0, (c + 1) * 16,
                        asu + (bufi ^ 1) * A_PITCH_BYTES,
                        bsu + (bufi ^ 1) * B_PITCH_BYTES, t);
            asm volatile("cp.async.wait_group 1;" ::: "memory");
        } else {
            asm volatile("cp.async.wait_group 0;" ::: "memory");
        }
        __syncthreads();

        const uint32_t a_s = asu + bufi * A_PITCH_BYTES;
        const uint32_t b_s = bsu + bufi * B_PITCH_BYTES;
        uint32_t ah[2][4], al[2][4], bh[2][4], bl[2][4];
        #pragma unroll
        for (int mt = 0; mt < 2; mt++) {
            const uint32_t base = a_s + (uint32_t)(arow + mt * 16) * 80 + koff;
            ldsm4(ah[mt], base);
            ldsm4(al[mt], base + 32);
        }
        #pragma unroll
        for (int g = 0; g < 2; g++) {
            const uint32_t base = b_s + (uint32_t)(brow + g * 16) * 80 + koff;
            ldsm4(bh[g], base);
            ldsm4(bl[g], base + 32);
        }
        #pragma unroll
        for (int mt = 0; mt < 2; mt++)
            #pragma unroll
            for (int nt = 0; nt < 4; nt++) {
                const int g = nt >> 1, s = nt & 1;
                mma_bf16(acc[mt][nt], ah[mt], bh[g][s], bh[g][s + 2]);
                mma_bf16(acc[mt][nt], ah[mt], bl[g][s], bl[g][s + 2]);
                mma_bf16(acc[mt][nt], al[mt], bh[g][s], bh[g][s + 2]);
            }
        __syncthreads();
    }
}

// ---------------------------------------------------------------------------
// Kernel 1: per (b,i) — histogram labels, build W (bf16 hi/lo), copy hidden
// row into agg slot 4 (bf16 hi/lo). grid = B*S, 256 threads.
// ---------------------------------------------------------------------------
__global__ void build_w_kernel(const float* __restrict__ hidden,
                               const int*   __restrict__ rels,
                               const float* __restrict__ rel_weight) {
    const int bi = blockIdx.x;
    const int b = bi >> 8;
    const int i = bi & 255;
    const int t = threadIdx.x;

    __shared__ int   cf[32], cr[32];
    __shared__ float inv_f[32], inv_r[32];
    __shared__ float rw[64 * 4];

    if (t < 32) { cf[t] = 0; cr[t] = 0; }
    rw[t] = rel_weight[t];
    __syncthreads();

    const int lf = rels[(b * S_ + i) * S_ + t];
    const int lr = rels[(b * S_ + t) * S_ + i];
    if (lf > 0) atomicAdd(&cf[lf], 1);
    if (lr > 0) atomicAdd(&cr[lr], 1);
    __syncthreads();

    if (t < 32) {
        inv_f[t] = 1.0f / (float)(cf[t] > 0 ? cf[t] : 1);
        inv_r[t] = 1.0f / (float)(cr[t] > 0 ? cr[t] : 1);
    }
    __syncthreads();

    float w[4] = {0.f, 0.f, 0.f, 0.f};
    if (lf > 0) {
        const float s = inv_f[lf];
        #pragma unroll
        for (int c = 0; c < 4; c++) w[c] += rw[lf * 4 + c] * s;
    }
    if (lr > 0) {
        const float s = inv_r[lr];
        #pragma unroll
        for (int c = 0; c < 4; c++) w[c] += rw[(lr + 32) * 4 + c] * s;
    }
    #pragma unroll
    for (int c = 0; c < 4; c++) {
        size_t idx = ((size_t)((b * 4 + c) * S_ + i)) * S_ + t;
        __nv_bfloat16 h, l; split_bf16(w[c], h, l);
        g_Whi[idx] = h; g_Wlo[idx] = l;
    }

    const float* hrow = hidden + (size_t)(b * S_ + i) * H_;
    size_t rb = (size_t)(b * S_ + i) * KTOT + 4 * H_;
    #pragma unroll
    for (int u = 0; u < 3; u++) {
        float v = hrow[t + 256 * u];
        __nv_bfloat16 h, l; split_bf16(v, h, l);
        g_agghi[rb + t + 256 * u] = h;
        g_agglo[rb + t + 256 * u] = l;
    }
}

// Kernel 1b: hiddenT[b,h,s] = hidden[b,s,h], bf16 hi/lo.
__global__ void t_hidden_kernel(const float* __restrict__ hid) {
    __shared__ float tile[32][33];
    const int b = blockIdx.z;
    const int h0 = blockIdx.x * 32, s0 = blockIdx.y * 32;
    const int tx = threadIdx.x, ty = threadIdx.y;
    #pragma unroll
    for (int r = 0; r < 4; r++)
        tile[ty + 8 * r][tx] = hid[(size_t)(b * S_ + s0 + ty + 8 * r) * H_ + h0 + tx];
    __syncthreads();
    #pragma unroll
    for (int r = 0; r < 4; r++) {
        float v = tile[tx][ty + 8 * r];
        size_t o = ((size_t)b * H_ + h0 + ty + 8 * r) * S_ + s0 + tx;
        __nv_bfloat16 h, l; split_bf16(v, h, l);
        g_hThi[o] = h; g_hTlo[o] = l;
    }
}

// Kernel 1c: BopT[n,k]: k<3072 -> basic[k,n] transpose, else self_w[n,k-3072].
__global__ void t_bop_kernel(const float* __restrict__ basic,
                             const float* __restrict__ selfw) {
    const int kt = blockIdx.x * 32, nt = blockIdx.y * 32;
    const int tx = threadIdx.x, ty = threadIdx.y;
    if (kt >= 3072) {
        #pragma unroll
        for (int r = 0; r < 4; r++) {
            int n = nt + ty + 8 * r, k = kt + tx;
            float v = selfw[(size_t)n * H_ + (k - 3072)];
            size_t o = (size_t)n * KTOT + k;
            __nv_bfloat16 h, l; split_bf16(v, h, l);
            g_bThi[o] = h; g_bTlo[o] = l;
        }
    } else {
        __shared__ float tile[32][33];
        #pragma unroll
        for (int r = 0; r < 4; r++)
            tile[ty + 8 * r][tx] = basic[(size_t)(kt + ty + 8 * r) * H_ + nt + tx];
        __syncthreads();
        #pragma unroll
        for (int r = 0; r < 4; r++) {
            float v = tile[tx][ty + 8 * r];
            size_t o = (size_t)(nt + ty + 8 * r) * KTOT + kt + tx;
            __nv_bfloat16 h, l; split_bf16(v, h, l);
            g_bThi[o] = h; g_bTlo[o] = l;
        }
    }
}

// ---------------------------------------------------------------------------
// GEMM1: agg[b*256+i, cb*768+n] = W[b,cb] (256x256) @ hiddenT (768x256)^T
// grid (768/64, 256/128, 16) = (12, 2, 16), 256 thr.
// ---------------------------------------------------------------------------
__global__ __launch_bounds__(256, 2) void gemm1_kernel() {
    __shared__ __align__(128) char smA[2 * A_PITCH_BYTES];
    __shared__ __align__(128) char smB[2 * B_PITCH_BYTES];
    const int n0 = blockIdx.x * 64;
    const int m0 = blockIdx.y * 128;
    const int bc = blockIdx.z, b = bc >> 2, cb = bc & 3;

    float acc[2][4][4] = {};
    gemm_core<16>(g_Whi + (size_t)bc * 65536, g_Wlo + (size_t)bc * 65536, 256,
                  g_hThi + (size_t)b * H_ * S_, g_hTlo + (size_t)b * H_ * S_, 256,
                  m0, n0, s2u(smA), s2u(smB), acc);

    const int t = threadIdx.x, lane = t & 31, wid = t >> 5;
    const int wm = wid & 3, wn = wid >> 2;
    #pragma unroll
    for (int mt = 0; mt < 2; mt++)
        #pragma unroll
        for (int nt = 0; nt < 4; nt++) {
            const int row = m0 + wm * 32 + mt * 16 + (lane >> 2);
            const int col = cb * H_ + n0 + wn * 32 + nt * 8 + (lane & 3) * 2;
            const size_t o0 = (size_t)(b * S_ + row) * KTOT + col;
            const size_t o1 = (size_t)(b * S_ + row + 8) * KTOT + col;
            __nv_bfloat16 h0, l0, h1, l1;
            __nv_bfloat162 vh, vl;
            split_bf16(acc[mt][nt][0], h0, l0);
            split_bf16(acc[mt][nt][1], h1, l1);
            vh.x = h0; vh.y = h1; vl.x = l0; vl.y = l1;
            *reinterpret_cast<__nv_bfloat162*>(g_agghi + o0) = vh;
            *reinterpret_cast<__nv_bfloat162*>(g_agglo + o0) = vl;
            split_bf16(acc[mt][nt][2], h0, l0);
            split_bf16(acc[mt][nt][3], h1, l1);
            vh.x = h0; vh.y = h1; vl.x = l0; vl.y = l1;
            *reinterpret_cast<__nv_bfloat162*>(g_agghi + o1) = vh;
            *reinterpret_cast<__nv_bfloat162*>(g_agglo + o1) = vl;
        }
}

// ---------------------------------------------------------------------------
// GEMM2: out[1024,768] = agg[1024,3840] @ BopT^T. grid (12, 8), 256 thr.
// ---------------------------------------------------------------------------
__global__ __launch_bounds__(256, 2) void gemm2_kernel(float* __restrict__ out) {
    __shared__ __align__(128) char smA[2 * A_PITCH_BYTES];
    __shared__ __align__(128) char smB[2 * B_PITCH_BYTES];
    const int n0 = blockIdx.x * 64;
    const int m0 = blockIdx.y * 128;

    float acc[2][4][4] = {};
    gemm_core<240>(g_agghi, g_agglo, KTOT, g_bThi, g_bTlo, KTOT,
                   m0, n0, s2u(smA), s2u(smB), acc);

    const int t = threadIdx.x, lane = t & 31, wid = t >> 5;
    const int wm = wid & 3, wn = wid >> 2;
    #pragma unroll
    for (int mt = 0; mt < 2; mt++)
        #pragma unroll
        for (int nt = 0; nt < 4; nt++) {
            const int row = m0 + wm * 32 + mt * 16 + (lane >> 2);
            const int col = n0 + wn * 32 + nt * 8 + (lane & 3) * 2;
            float2 v0, v1;
            v0.x = acc[mt][nt][0]; v0.y = acc[mt][nt][1];
            v1.x = acc[mt][nt][2]; v1.y = acc[mt][nt][3];
            *reinterpret_cast<float2*>(out + (size_t)row * H_ + col) = v0;
            *reinterpret_cast<float2*>(out + (size_t)(row + 8) * H_ + col) = v1;
        }
}

// ---------------------------------------------------------------------------
extern "C" void kernel_launch(void* const* d_in, const int* in_sizes, int n_in,
                              void* d_out, int out_size) {
    const float* hidden     = (const float*)d_in[0]; // [4,256,768]
    const int*   rels       = (const int*)  d_in[1]; // [4,256,256]
    const float* basic      = (const float*)d_in[2]; // [4,768,768]
    const float* rel_weight = (const float*)d_in[3]; // [64,4]
    const float* self_w     = (const float*)d_in[4]; // [768,768] (out,in)
    float* out = (float*)d_out;                      // [4,256,768]

    build_w_kernel<<<B_ * S_, 256>>>(hidden, rels, rel_weight);
    t_hidden_kernel<<<dim3(H_ / 32, S_ / 32, B_), dim3(32, 8)>>>(hidden);
    t_bop_kernel<<<dim3(KTOT / 32, H_ / 32), dim3(32, 8)>>>(basic, self_w);
    gemm1_kernel<<<dim3(H_ / 64, S_ / 128, 16), 256>>>();
    gemm2_kernel<<<dim3(H_ / 64, (B_ * S_) / 128), 256>>>(out);
}

// round 4
// speedup vs baseline: 2.4052x; 1.2638x over previous
#include <cuda_runtime.h>
#include <cuda_bf16.h>
#include <cstdint>

#define B_   4
#define S_   256
#define H_   768
#define NTOT 3840   // 5*768 : 4 basis slots + self slot
#define KW   1024   // 4*256 : step-2 K (4 c-blocks of 256)

// ---------------- static device scratch -------------------------------------
__device__ __align__(256) __nv_bfloat16 g_hhi[B_ * S_ * H_];     // hidden split
__device__ __align__(256) __nv_bfloat16 g_hlo[B_ * S_ * H_];
__device__ __align__(256) __nv_bfloat16 g_bashi[4 * H_ * H_];    // basic split [c][h][o]
__device__ __align__(256) __nv_bfloat16 g_baslo[4 * H_ * H_];
__device__ __align__(256) __nv_bfloat16 g_selfhi[H_ * H_];       // selfw^T split [h][o]
__device__ __align__(256) __nv_bfloat16 g_selflo[H_ * H_];
__device__ __align__(256) __nv_bfloat16 g_Whi[B_ * S_ * KW];     // W [b][i][c*256+j]
__device__ __align__(256) __nv_bfloat16 g_Wlo[B_ * S_ * KW];
__device__ __align__(256) __nv_bfloat16 g_hbhi[B_ * S_ * NTOT];  // hb [b][s][n]
__device__ __align__(256) __nv_bfloat16 g_hblo[B_ * S_ * NTOT];

// ---------------- helpers ---------------------------------------------------
__device__ __forceinline__ uint32_t s2u(const void* p) {
    uint32_t a;
    asm("{ .reg .u64 t; cvta.to.shared.u64 t, %1; cvt.u32.u64 %0, t; }"
        : "=r"(a) : "l"(p));
    return a;
}
__device__ __forceinline__ void cp16(uint32_t dst, const void* src) {
    asm volatile("cp.async.cg.shared.global [%0], [%1], 16;"
                 :: "r"(dst), "l"(src) : "memory");
}
__device__ __forceinline__ void ldsm4(uint32_t* r, uint32_t addr) {
    asm volatile("ldmatrix.sync.aligned.m8n8.x4.shared.b16 {%0,%1,%2,%3}, [%4];"
                 : "=r"(r[0]), "=r"(r[1]), "=r"(r[2]), "=r"(r[3]) : "r"(addr));
}
__device__ __forceinline__ void ldsm4t(uint32_t* r, uint32_t addr) {
    asm volatile("ldmatrix.sync.aligned.m8n8.x4.trans.shared.b16 {%0,%1,%2,%3}, [%4];"
                 : "=r"(r[0]), "=r"(r[1]), "=r"(r[2]), "=r"(r[3]) : "r"(addr));
}
__device__ __forceinline__ void mma_bf16(float* d, const uint32_t* a,
                                         uint32_t b0, uint32_t b1) {
    asm volatile("mma.sync.aligned.m16n8k16.row.col.f32.bf16.bf16.f32 "
                 "{%0,%1,%2,%3}, {%4,%5,%6,%7}, {%8,%9}, {%0,%1,%2,%3};"
                 : "+f"(d[0]), "+f"(d[1]), "+f"(d[2]), "+f"(d[3])
                 : "r"(a[0]), "r"(a[1]), "r"(a[2]), "r"(a[3]), "r"(b0), "r"(b1));
}
__device__ __forceinline__ void split_bf16(float v, __nv_bfloat16& h, __nv_bfloat16& l) {
    h = __float2bfloat16_rn(v);
    l = __float2bfloat16_rn(v - __bfloat162float(h));
}

// ---------------- GEMM building blocks --------------------------------------
// SMEM A: MROWS rows x [hi 32B | lo 32B | pad 16B], pitch 80 (conflict-free).
// SMEM B: 16 k-rows x [hi 128B | lo 128B | pad 16B], pitch 272 (conflict-free
// for trans-ldmatrix: bank(68k mod 32) = 4k).
#define A_PITCH 80
#define B_PITCH 272
#define B_BUF   (16 * B_PITCH)

template<int MROWS, int NTH>
__device__ __forceinline__ void issue_chunk(
    const __nv_bfloat16* __restrict__ Ahi, const __nv_bfloat16* __restrict__ Alo, int lda,
    const __nv_bfloat16* __restrict__ Bhi, const __nv_bfloat16* __restrict__ Blo, int ldb,
    uint32_t a_s, uint32_t b_s, int t)
{
    #pragma unroll
    for (int u = 0; u < MROWS * 4 / NTH; u++) {
        const int id = t + NTH * u;
        const int r = id >> 2, q = id & 3;
        const __nv_bfloat16* sp = (q < 2) ? Ahi : Alo;
        cp16(a_s + r * A_PITCH + (q & 1) * 16 + (q >> 1) * 32,
             sp + (size_t)r * lda + (q & 1) * 8);
    }
    #pragma unroll
    for (int u = 0; u < 256 / NTH; u++) {
        const int id = t + NTH * u;
        const int k = id >> 4, q = id & 15;
        const __nv_bfloat16* sp = (q < 8) ? Bhi : Blo;
        cp16(b_s + k * B_PITCH + ((q & 8) ? 128 : 0) + (q & 7) * 16,
             sp + (size_t)k * ldb + (q & 7) * 8);
    }
    asm volatile("cp.async.commit_group;" ::: "memory");
}

__device__ __forceinline__ void compute_chunk(uint32_t a_s, uint32_t b_s,
                                              float acc[2][4][4],
                                              int lane, int wm, int wn)
{
    const int arow = wm * 32 + (lane & 15);
    const uint32_t akoff = (uint32_t)(lane >> 4) * 16;
    uint32_t ah[2][4], al[2][4], bh[2][4], bl[2][4];
    #pragma unroll
    for (int mt = 0; mt < 2; mt++) {
        const uint32_t base = a_s + (uint32_t)(arow + mt * 16) * A_PITCH + akoff;
        ldsm4(ah[mt], base);
        ldsm4(al[mt], base + 32);
    }
    // trans-ldmatrix B: lanes 0-7 k0-7/nlo, 8-15 k0-7/nhi, 16-23 k8-15/nlo, 24-31 k8-15/nhi
    const int krow = (lane & 7) | ((lane >> 1) & 8);
    const int noff = (lane & 8) ? 16 : 0;
    #pragma unroll
    for (int g = 0; g < 2; g++) {
        const uint32_t base = b_s + (uint32_t)krow * B_PITCH + (uint32_t)(wn * 64 + g * 32) + noff;
        ldsm4t(bh[g], base);
        ldsm4t(bl[g], base + 128);
    }
    #pragma unroll
    for (int mt = 0; mt < 2; mt++)
        #pragma unroll
        for (int nt = 0; nt < 4; nt++) {
            const int g = nt >> 1, s = nt & 1;
            mma_bf16(acc[mt][nt], ah[mt], bh[g][s], bh[g][s + 2]);
            mma_bf16(acc[mt][nt], ah[mt], bl[g][s], bl[g][s + 2]);
            mma_bf16(acc[mt][nt], al[mt], bh[g][s], bh[g][s + 2]);
        }
}

// ---------------------------------------------------------------------------
// Prep: elementwise fp32 -> bf16 hi/lo split (vectorized).
// ---------------------------------------------------------------------------
__global__ void split_kernel(const float* __restrict__ src,
                             __nv_bfloat16* __restrict__ hi,
                             __nv_bfloat16* __restrict__ lo) {
    const int i = blockIdx.x * blockDim.x + threadIdx.x;
    float4 v = reinterpret_cast<const float4*>(src)[i];
    __nv_bfloat16 h0, l0, h1, l1;
    __nv_bfloat162 vh, vl;
    split_bf16(v.x, h0, l0); split_bf16(v.y, h1, l1);
    vh.x = h0; vh.y = h1; vl.x = l0; vl.y = l1;
    reinterpret_cast<__nv_bfloat162*>(hi)[i * 2] = vh;
    reinterpret_cast<__nv_bfloat162*>(lo)[i * 2] = vl;
    split_bf16(v.z, h0, l0); split_bf16(v.w, h1, l1);
    vh.x = h0; vh.y = h1; vl.x = l0; vl.y = l1;
    reinterpret_cast<__nv_bfloat162*>(hi)[i * 2 + 1] = vh;
    reinterpret_cast<__nv_bfloat162*>(lo)[i * 2 + 1] = vl;
}

// Prep: selfT[h][o] = selfw[o][h], split.
__global__ void t_self_kernel(const float* __restrict__ sw) {
    __shared__ float tile[32][33];
    const int h0 = blockIdx.x * 32, o0 = blockIdx.y * 32;
    const int tx = threadIdx.x, ty = threadIdx.y;
    #pragma unroll
    for (int r = 0; r < 4; r++)
        tile[ty + 8 * r][tx] = sw[(size_t)(o0 + ty + 8 * r) * H_ + h0 + tx];
    __syncthreads();
    #pragma unroll
    for (int r = 0; r < 4; r++) {
        float v = tile[tx][ty + 8 * r];
        size_t o = (size_t)(h0 + ty + 8 * r) * H_ + o0 + tx;
        __nv_bfloat16 h, l; split_bf16(v, h, l);
        g_selfhi[o] = h; g_selflo[o] = l;
    }
}

// ---------------------------------------------------------------------------
// build_w: histogram + W[b][i][c*256+j] (bf16 hi/lo). grid B*S, 256 thr.
// ---------------------------------------------------------------------------
__global__ void build_w_kernel(const int* __restrict__ rels,
                               const float* __restrict__ rel_weight) {
    const int bi = blockIdx.x;
    const int b = bi >> 8;
    const int i = bi & 255;
    const int t = threadIdx.x;

    __shared__ int   cf[32], cr[32];
    __shared__ float inv_f[32], inv_r[32];
    __shared__ float rw[64 * 4];

    if (t < 32) { cf[t] = 0; cr[t] = 0; }
    rw[t] = rel_weight[t];
    __syncthreads();

    const int lf = rels[(b * S_ + i) * S_ + t];
    const int lr = rels[(b * S_ + t) * S_ + i];
    if (lf > 0) atomicAdd(&cf[lf], 1);
    if (lr > 0) atomicAdd(&cr[lr], 1);
    __syncthreads();

    if (t < 32) {
        inv_f[t] = 1.0f / (float)(cf[t] > 0 ? cf[t] : 1);
        inv_r[t] = 1.0f / (float)(cr[t] > 0 ? cr[t] : 1);
    }
    __syncthreads();

    float w[4] = {0.f, 0.f, 0.f, 0.f};
    if (lf > 0) {
        const float s = inv_f[lf];
        #pragma unroll
        for (int c = 0; c < 4; c++) w[c] += rw[lf * 4 + c] * s;
    }
    if (lr > 0) {
        const float s = inv_r[lr];
        #pragma unroll
        for (int c = 0; c < 4; c++) w[c] += rw[(lr + 32) * 4 + c] * s;
    }
    #pragma unroll
    for (int c = 0; c < 4; c++) {
        size_t idx = ((size_t)(b * S_ + i)) * KW + c * 256 + t;
        __nv_bfloat16 h, l; split_bf16(w[c], h, l);
        g_Whi[idx] = h; g_Wlo[idx] = l;
    }
}

// ---------------------------------------------------------------------------
// GEMM-HB: hb[b] (256x3840) = hidden[b] (256x768) @ [basic|selfT] (768x3840)
// grid (60, 2, 4) = 480 CTAs, 256 thr, CTA tile 128x64, K=768 (48 chunks).
// ---------------------------------------------------------------------------
__global__ __launch_bounds__(256, 2) void gemm_hb_kernel() {
    __shared__ __align__(128) char smA[2 * 128 * A_PITCH];
    __shared__ __align__(128) char smB[2 * B_BUF];
    const int n0 = blockIdx.x * 64;   // 0..3840
    const int m0 = blockIdx.y * 128;
    const int b  = blockIdx.z;
    const int cslot = n0 / 768;
    const int o0 = n0 - cslot * 768;

    const __nv_bfloat16* Ah = g_hhi + ((size_t)(b * S_ + m0)) * H_;
    const __nv_bfloat16* Al = g_hlo + ((size_t)(b * S_ + m0)) * H_;
    const __nv_bfloat16* Bh = (cslot < 4) ? g_bashi + (size_t)cslot * H_ * H_ + o0
                                          : g_selfhi + o0;
    const __nv_bfloat16* Bl = (cslot < 4) ? g_baslo + (size_t)cslot * H_ * H_ + o0
                                          : g_selflo + o0;

    const int t = threadIdx.x, lane = t & 31, wid = t >> 5;
    const int wm = wid & 3, wn = wid >> 2;
    const uint32_t asu = s2u(smA), bsu = s2u(smB);

    float acc[2][4][4] = {};
    issue_chunk<128, 256>(Ah, Al, H_, Bh, Bl, H_, asu, bsu, t);
    const int NC = 48;
    for (int c = 0; c < NC; c++) {
        const int bufi = c & 1;
        if (c + 1 < NC) {
            const int k0 = (c + 1) * 16;
            issue_chunk<128, 256>(Ah + k0, Al + k0, H_,
                                  Bh + (size_t)k0 * H_, Bl + (size_t)k0 * H_, H_,
                                  asu + (bufi ^ 1) * (128 * A_PITCH),
                                  bsu + (bufi ^ 1) * B_BUF, t);
            asm volatile("cp.async.wait_group 1;" ::: "memory");
        } else {
            asm volatile("cp.async.wait_group 0;" ::: "memory");
        }
        __syncthreads();
        compute_chunk(asu + bufi * (128 * A_PITCH), bsu + bufi * B_BUF, acc, lane, wm, wn);
        __syncthreads();
    }

    // epilogue: split -> g_hb (n-contig)
    #pragma unroll
    for (int mt = 0; mt < 2; mt++)
        #pragma unroll
        for (int nt = 0; nt < 4; nt++) {
            const int row = m0 + wm * 32 + mt * 16 + (lane >> 2);
            const int col = n0 + wn * 32 + nt * 8 + (lane & 3) * 2;
            const size_t o0i = (size_t)(b * S_ + row) * NTOT + col;
            const size_t o1i = (size_t)(b * S_ + row + 8) * NTOT + col;
            __nv_bfloat16 h0, l0, h1, l1;
            __nv_bfloat162 vh, vl;
            split_bf16(acc[mt][nt][0], h0, l0);
            split_bf16(acc[mt][nt][1], h1, l1);
            vh.x = h0; vh.y = h1; vl.x = l0; vl.y = l1;
            *reinterpret_cast<__nv_bfloat162*>(g_hbhi + o0i) = vh;
            *reinterpret_cast<__nv_bfloat162*>(g_hblo + o0i) = vl;
            split_bf16(acc[mt][nt][2], h0, l0);
            split_bf16(acc[mt][nt][3], h1, l1);
            vh.x = h0; vh.y = h1; vl.x = l0; vl.y = l1;
            *reinterpret_cast<__nv_bfloat162*>(g_hbhi + o1i) = vh;
            *reinterpret_cast<__nv_bfloat162*>(g_hblo + o1i) = vl;
        }
}

// ---------------------------------------------------------------------------
// GEMM-OUT: out[b] (256x768) = W[b] (256x1024) @ hb_stack (1024x768) + self
// grid (12, 4, 4) = 192 CTAs, 128 thr, CTA tile 64x64, K=1024 (64 chunks).
// B row k=(c*256+j) -> hb[b][j][c*768+n].
// ---------------------------------------------------------------------------
__global__ __launch_bounds__(128, 2) void gemm_out_kernel(float* __restrict__ out) {
    __shared__ __align__(128) char smA[2 * 64 * A_PITCH];
    __shared__ __align__(128) char smB[2 * B_BUF];
    const int n0 = blockIdx.x * 64;
    const int m0 = blockIdx.y * 64;
    const int b  = blockIdx.z;

    const __nv_bfloat16* Ah = g_Whi + ((size_t)(b * S_ + m0)) * KW;
    const __nv_bfloat16* Al = g_Wlo + ((size_t)(b * S_ + m0)) * KW;
    const __nv_bfloat16* hbh = g_hbhi + (size_t)b * S_ * NTOT + n0;
    const __nv_bfloat16* hbl = g_hblo + (size_t)b * S_ * NTOT + n0;

    const int t = threadIdx.x, lane = t & 31, wid = t >> 5;
    const int wm = wid & 1, wn = wid >> 1;
    const uint32_t asu = s2u(smA), bsu = s2u(smB);

    float acc[2][4][4] = {};
    issue_chunk<64, 128>(Ah, Al, KW, hbh, hbl, NTOT, asu, bsu, t);
    const int NC = 64;
    for (int c = 0; c < NC; c++) {
        const int bufi = c & 1;
        if (c + 1 < NC) {
            const int k0 = (c + 1) * 16;
            const size_t boff = (size_t)(k0 >> 8) * 768 + (size_t)(k0 & 255) * NTOT;
            issue_chunk<64, 128>(Ah + k0, Al + k0, KW,
                                 hbh + boff, hbl + boff, NTOT,
                                 asu + (bufi ^ 1) * (64 * A_PITCH),
                                 bsu + (bufi ^ 1) * B_BUF, t);
            asm volatile("cp.async.wait_group 1;" ::: "memory");
        } else {
            asm volatile("cp.async.wait_group 0;" ::: "memory");
        }
        __syncthreads();
        compute_chunk(asu + bufi * (64 * A_PITCH), bsu + bufi * B_BUF, acc, lane, wm, wn);
        __syncthreads();
    }

    // epilogue: add self slot (hb[:, 3072+n]) and store fp32
    #pragma unroll
    for (int mt = 0; mt < 2; mt++)
        #pragma unroll
        for (int nt = 0; nt < 4; nt++) {
            const int row = m0 + wm * 32 + mt * 16 + (lane >> 2);
            const int col = n0 + wn * 32 + nt * 8 + (lane & 3) * 2;
            #pragma unroll
            for (int half = 0; half < 2; half++) {
                const int r = row + half * 8;
                const size_t so = (size_t)(b * S_ + r) * NTOT + 3072 + col;
                __nv_bfloat162 sh = *reinterpret_cast<const __nv_bfloat162*>(g_hbhi + so);
                __nv_bfloat162 sl = *reinterpret_cast<const __nv_bfloat162*>(g_hblo + so);
                float2 v;
                v.x = acc[mt][nt][half * 2 + 0] + __bfloat162float(sh.x) + __bfloat162float(sl.x);
                v.y = acc[mt][nt][half * 2 + 1] + __bfloat162float(sh.y) + __bfloat162float(sl.y);
                *reinterpret_cast<float2*>(out + (size_t)(b * S_ + r) * H_ + col) = v;
            }
        }
}

// ---------------------------------------------------------------------------
extern "C" void kernel_launch(void* const* d_in, const int* in_sizes, int n_in,
                              void* d_out, int out_size) {
    const float* hidden     = (const float*)d_in[0]; // [4,256,768]
    const int*   rels       = (const int*)  d_in[1]; // [4,256,256]
    const float* basic      = (const float*)d_in[2]; // [4,768,768]
    const float* rel_weight = (const float*)d_in[3]; // [64,4]
    const float* self_w     = (const float*)d_in[4]; // [768,768] (out,in)
    float* out = (float*)d_out;                      // [4,256,768]

    __nv_bfloat16 *hhi, *hlo, *bashi, *baslo;
    cudaGetSymbolAddress((void**)&hhi, g_hhi);
    cudaGetSymbolAddress((void**)&hlo, g_hlo);
    cudaGetSymbolAddress((void**)&bashi, g_bashi);
    cudaGetSymbolAddress((void**)&baslo, g_baslo);

    split_kernel<<<(B_ * S_ * H_) / 4 / 256, 256>>>(hidden, hhi, hlo);
    split_kernel<<<(4 * H_ * H_) / 4 / 256, 256>>>(basic, bashi, baslo);
    t_self_kernel<<<dim3(H_ / 32, H_ / 32), dim3(32, 8)>>>(self_w);
    build_w_kernel<<<B_ * S_, 256>>>(rels, rel_weight);
    gemm_hb_kernel<<<dim3(NTOT / 64, S_ / 128, B_), 256>>>();
    gemm_out_kernel<<<dim3(H_ / 64, S_ / 64, B_), 128>>>(out);
}

// round 5
// speedup vs baseline: 5.6949x; 2.3677x over previous
#include <cuda_runtime.h>
#include <cuda_fp16.h>
#include <cstdint>

#define B_   4
#define S_   256
#define H_   768
#define NTOT 3840   // 5*768 : 4 basis slots + self slot
#define KW   1024   // 4*256 : step-2 K (4 c-blocks of 256)

// ---------------- static device scratch -------------------------------------
__device__ __align__(256) __half g_h[B_ * S_ * H_];      // hidden fp16
__device__ __align__(256) __half g_bas[4 * H_ * H_];     // basic fp16 [c][h][o]
__device__ __align__(256) __half g_self[H_ * H_];        // selfw^T fp16 [h][o]
__device__ __align__(256) __half g_W[B_ * S_ * KW];      // W [b][i][c*256+j]
__device__ __align__(256) __half g_hb[B_ * S_ * NTOT];   // hb [b][s][n]

// ---------------- helpers ---------------------------------------------------
__device__ __forceinline__ uint32_t s2u(const void* p) {
    uint32_t a;
    asm("{ .reg .u64 t; cvta.to.shared.u64 t, %1; cvt.u32.u64 %0, t; }"
        : "=r"(a) : "l"(p));
    return a;
}
__device__ __forceinline__ void cp16(uint32_t dst, const void* src) {
    asm volatile("cp.async.cg.shared.global [%0], [%1], 16;"
                 :: "r"(dst), "l"(src) : "memory");
}
__device__ __forceinline__ void ldsm4(uint32_t* r, uint32_t addr) {
    asm volatile("ldmatrix.sync.aligned.m8n8.x4.shared.b16 {%0,%1,%2,%3}, [%4];"
                 : "=r"(r[0]), "=r"(r[1]), "=r"(r[2]), "=r"(r[3]) : "r"(addr));
}
__device__ __forceinline__ void ldsm4t(uint32_t* r, uint32_t addr) {
    asm volatile("ldmatrix.sync.aligned.m8n8.x4.trans.shared.b16 {%0,%1,%2,%3}, [%4];"
                 : "=r"(r[0]), "=r"(r[1]), "=r"(r[2]), "=r"(r[3]) : "r"(addr));
}
__device__ __forceinline__ void mma_f16(float* d, const uint32_t* a,
                                        uint32_t b0, uint32_t b1) {
    asm volatile("mma.sync.aligned.m16n8k16.row.col.f32.f16.f16.f32 "
                 "{%0,%1,%2,%3}, {%4,%5,%6,%7}, {%8,%9}, {%0,%1,%2,%3};"
                 : "+f"(d[0]), "+f"(d[1]), "+f"(d[2]), "+f"(d[3])
                 : "r"(a[0]), "r"(a[1]), "r"(a[2]), "r"(a[3]), "r"(b0), "r"(b1));
}

// ---------------- SMEM layout ------------------------------------------------
// A: rows of 32B (16 halves), pitch 48 -> ldsm banks 12r mod 32 conflict-free.
// B: 16 k-rows of n*2 bytes + 16B pad -> pitch = data+16; (data+16)/4*k mod 32
//    = 4k pattern for both 272 (128n) and 144 (64n): conflict-free trans ldsm.
#define A_PITCH 48

// ---------------- generic chunk loaders --------------------------------------
// A tile: MROWS x 16 halves. B tile: 16 x NCOLS halves.
template<int MROWS, int NCOLS, int BP, int NTH>
__device__ __forceinline__ void issue_chunk(
    const __half* __restrict__ A, int lda,
    const __half* __restrict__ Bm, int ldb,
    uint32_t a_s, uint32_t b_s, int t)
{
    #pragma unroll
    for (int u = 0; u < MROWS * 2 / NTH; u++) {
        const int id = t + NTH * u;
        const int r = id >> 1, seg = id & 1;
        cp16(a_s + r * A_PITCH + seg * 16, A + (size_t)r * lda + seg * 8);
    }
    #pragma unroll
    for (int u = 0; u < 16 * (NCOLS / 8) / NTH; u++) {
        const int id = t + NTH * u;
        const int k = id / (NCOLS / 8), q = id % (NCOLS / 8);
        cp16(b_s + k * BP + q * 16, Bm + (size_t)k * ldb + q * 8);
    }
    asm volatile("cp.async.commit_group;" ::: "memory");
}

// NG groups of 16 n per warp (warp tile = 32 x NG*16).
template<int BP, int NG>
__device__ __forceinline__ void compute_chunk(uint32_t a_s, uint32_t b_s,
                                              float acc[2][NG * 2][4],
                                              int lane, int wm, int wn)
{
    const int arow = wm * 32 + (lane & 15);
    const uint32_t abase = a_s + (uint32_t)arow * A_PITCH + (uint32_t)(lane >> 4) * 16;
    uint32_t ah[2][4], bh[NG][4];
    ldsm4(ah[0], abase);
    ldsm4(ah[1], abase + 16 * A_PITCH);
    const int krow = (lane & 7) | ((lane >> 1) & 8);
    const int noff = (lane & 8) ? 16 : 0;
    #pragma unroll
    for (int g = 0; g < NG; g++)
        ldsm4t(bh[g], b_s + (uint32_t)krow * BP + (uint32_t)(wn * (NG * 32) + g * 32) + noff);
    #pragma unroll
    for (int mt = 0; mt < 2; mt++)
        #pragma unroll
        for (int g = 0; g < NG; g++)
            #pragma unroll
            for (int s = 0; s < 2; s++)
                mma_f16(acc[mt][g * 2 + s], ah[mt], bh[g][s], bh[g][s + 2]);
}

// ---------------------------------------------------------------------------
// Prep: fp32 -> fp16 convert (vectorized).
// ---------------------------------------------------------------------------
__global__ void cvt_kernel(const float* __restrict__ src, __half* __restrict__ dst) {
    const int i = blockIdx.x * blockDim.x + threadIdx.x;
    float4 v = reinterpret_cast<const float4*>(src)[i];
    __half2 a = __floats2half2_rn(v.x, v.y);
    __half2 b = __floats2half2_rn(v.z, v.w);
    reinterpret_cast<__half2*>(dst)[i * 2] = a;
    reinterpret_cast<__half2*>(dst)[i * 2 + 1] = b;
}

// Prep: selfT[h][o] = selfw[o][h], fp16.
__global__ void t_self_kernel(const float* __restrict__ sw) {
    __shared__ float tile[32][33];
    const int h0 = blockIdx.x * 32, o0 = blockIdx.y * 32;
    const int tx = threadIdx.x, ty = threadIdx.y;
    #pragma unroll
    for (int r = 0; r < 4; r++)
        tile[ty + 8 * r][tx] = sw[(size_t)(o0 + ty + 8 * r) * H_ + h0 + tx];
    __syncthreads();
    #pragma unroll
    for (int r = 0; r < 4; r++)
        g_self[(size_t)(h0 + ty + 8 * r) * H_ + o0 + tx] = __float2half(tile[tx][ty + 8 * r]);
}

// ---------------------------------------------------------------------------
// build_w: histogram + W[b][i][c*256+j] fp16. grid B*S, 256 thr.
// ---------------------------------------------------------------------------
__global__ void build_w_kernel(const int* __restrict__ rels,
                               const float* __restrict__ rel_weight) {
    const int bi = blockIdx.x;
    const int b = bi >> 8;
    const int i = bi & 255;
    const int t = threadIdx.x;

    __shared__ int   cf[32], cr[32];
    __shared__ float inv_f[32], inv_r[32];
    __shared__ float rw[64 * 4];

    if (t < 32) { cf[t] = 0; cr[t] = 0; }
    rw[t] = rel_weight[t];
    __syncthreads();

    const int lf = rels[(b * S_ + i) * S_ + t];
    const int lr = rels[(b * S_ + t) * S_ + i];
    if (lf > 0) atomicAdd(&cf[lf], 1);
    if (lr > 0) atomicAdd(&cr[lr], 1);
    __syncthreads();

    if (t < 32) {
        inv_f[t] = 1.0f / (float)(cf[t] > 0 ? cf[t] : 1);
        inv_r[t] = 1.0f / (float)(cr[t] > 0 ? cr[t] : 1);
    }
    __syncthreads();

    float w[4] = {0.f, 0.f, 0.f, 0.f};
    if (lf > 0) {
        const float s = inv_f[lf];
        #pragma unroll
        for (int c = 0; c < 4; c++) w[c] += rw[lf * 4 + c] * s;
    }
    if (lr > 0) {
        const float s = inv_r[lr];
        #pragma unroll
        for (int c = 0; c < 4; c++) w[c] += rw[(lr + 32) * 4 + c] * s;
    }
    #pragma unroll
    for (int c = 0; c < 4; c++)
        g_W[((size_t)(b * S_ + i)) * KW + c * 256 + t] = __float2half(w[c]);
}

// ---------------------------------------------------------------------------
// GEMM-HB: hb[b] (256x3840) = hidden[b] (256x768) @ [basic|selfT] (768x3840)
// grid (30, 2, 4) = 240 CTAs, 256 thr, CTA tile 128x128, warp tile 32x64.
// ---------------------------------------------------------------------------
#define HB_BP   272
#define HB_ABUF (128 * A_PITCH)
#define HB_BBUF (16 * HB_BP)

__global__ __launch_bounds__(256, 2) void gemm_hb_kernel() {
    __shared__ __align__(128) char smA[2 * HB_ABUF];
    __shared__ __align__(128) char smB[2 * HB_BBUF];
    const int n0 = blockIdx.x * 128;     // 0..3840, never straddles a 768-slot
    const int m0 = blockIdx.y * 128;
    const int b  = blockIdx.z;
    const int cslot = n0 / 768;
    const int o0 = n0 - cslot * 768;

    const __half* A  = g_h + ((size_t)(b * S_ + m0)) * H_;
    const __half* Bm = (cslot < 4) ? g_bas + (size_t)cslot * H_ * H_ + o0
                                   : g_self + o0;

    const int t = threadIdx.x, lane = t & 31, wid = t >> 5;
    const int wm = wid & 3, wn = wid >> 2;
    const uint32_t asu = s2u(smA), bsu = s2u(smB);

    float acc[2][8][4] = {};
    issue_chunk<128, 128, HB_BP, 256>(A, H_, Bm, H_, asu, bsu, t);
    const int NC = 48;
    for (int c = 0; c < NC; c++) {
        const int bufi = c & 1;
        if (c + 1 < NC) {
            const int k0 = (c + 1) * 16;
            issue_chunk<128, 128, HB_BP, 256>(A + k0, H_, Bm + (size_t)k0 * H_, H_,
                                              asu + (bufi ^ 1) * HB_ABUF,
                                              bsu + (bufi ^ 1) * HB_BBUF, t);
            asm volatile("cp.async.wait_group 1;" ::: "memory");
        } else {
            asm volatile("cp.async.wait_group 0;" ::: "memory");
        }
        __syncthreads();
        compute_chunk<HB_BP, 4>(asu + bufi * HB_ABUF, bsu + bufi * HB_BBUF,
                                acc, lane, wm, wn);
        __syncthreads();
    }

    #pragma unroll
    for (int mt = 0; mt < 2; mt++)
        #pragma unroll
        for (int nt = 0; nt < 8; nt++) {
            const int row = m0 + wm * 32 + mt * 16 + (lane >> 2);
            const int col = n0 + wn * 64 + nt * 8 + (lane & 3) * 2;
            *reinterpret_cast<__half2*>(g_hb + (size_t)(b * S_ + row) * NTOT + col) =
                __floats2half2_rn(acc[mt][nt][0], acc[mt][nt][1]);
            *reinterpret_cast<__half2*>(g_hb + (size_t)(b * S_ + row + 8) * NTOT + col) =
                __floats2half2_rn(acc[mt][nt][2], acc[mt][nt][3]);
        }
}

// ---------------------------------------------------------------------------
// GEMM-OUT: out[b] (256x768) = W[b] (256x1024) @ hb_stack (1024x768) + self
// grid (12, 4, 4) = 192 CTAs, 128 thr, CTA tile 64x64, warp tile 32x32.
// B row k=(c*256+j) -> hb[b][j][c*768+n].
// ---------------------------------------------------------------------------
#define OUT_BP   144
#define OUT_ABUF (64 * A_PITCH)
#define OUT_BBUF (16 * OUT_BP)

__global__ __launch_bounds__(128, 2) void gemm_out_kernel(float* __restrict__ out) {
    __shared__ __align__(128) char smA[2 * OUT_ABUF];
    __shared__ __align__(128) char smB[2 * OUT_BBUF];
    const int n0 = blockIdx.x * 64;
    const int m0 = blockIdx.y * 64;
    const int b  = blockIdx.z;

    const __half* A  = g_W + ((size_t)(b * S_ + m0)) * KW;
    const __half* hb = g_hb + (size_t)b * S_ * NTOT + n0;

    const int t = threadIdx.x, lane = t & 31, wid = t >> 5;
    const int wm = wid & 1, wn = wid >> 1;
    const uint32_t asu = s2u(smA), bsu = s2u(smB);

    float acc[2][4][4] = {};
    issue_chunk<64, 64, OUT_BP, 128>(A, KW, hb, NTOT, asu, bsu, t);
    const int NC = 64;
    for (int c = 0; c < NC; c++) {
        const int bufi = c & 1;
        if (c + 1 < NC) {
            const int k0 = (c + 1) * 16;
            const size_t boff = (size_t)(k0 >> 8) * 768 + (size_t)(k0 & 255) * NTOT;
            issue_chunk<64, 64, OUT_BP, 128>(A + k0, KW, hb + boff, NTOT,
                                             asu + (bufi ^ 1) * OUT_ABUF,
                                             bsu + (bufi ^ 1) * OUT_BBUF, t);
            asm volatile("cp.async.wait_group 1;" ::: "memory");
        } else {
            asm volatile("cp.async.wait_group 0;" ::: "memory");
        }
        __syncthreads();
        compute_chunk<OUT_BP, 2>(asu + bufi * OUT_ABUF, bsu + bufi * OUT_BBUF,
                                 acc, lane, wm, wn);
        __syncthreads();
    }

    // epilogue: add self slot (hb[:, 3072+n]) and store fp32
    #pragma unroll
    for (int mt = 0; mt < 2; mt++)
        #pragma unroll
        for (int nt = 0; nt < 4; nt++) {
            const int row = m0 + wm * 32 + mt * 16 + (lane >> 2);
            const int col = n0 + wn * 32 + nt * 8 + (lane & 3) * 2;
            #pragma unroll
            for (int half = 0; half < 2; half++) {
                const int r = row + half * 8;
                __half2 sh = *reinterpret_cast<const __half2*>(
                    g_hb + (size_t)(b * S_ + r) * NTOT + 3072 + col);
                float2 v;
                v.x = acc[mt][nt][half * 2 + 0] + __half2float(sh.x);
                v.y = acc[mt][nt][half * 2 + 1] + __half2float(sh.y);
                *reinterpret_cast<float2*>(out + (size_t)(b * S_ + r) * H_ + col) = v;
            }
        }
}

// ---------------------------------------------------------------------------
extern "C" void kernel_launch(void* const* d_in, const int* in_sizes, int n_in,
                              void* d_out, int out_size) {
    const float* hidden     = (const float*)d_in[0]; // [4,256,768]
    const int*   rels       = (const int*)  d_in[1]; // [4,256,256]
    const float* basic      = (const float*)d_in[2]; // [4,768,768]
    const float* rel_weight = (const float*)d_in[3]; // [64,4]
    const float* self_w     = (const float*)d_in[4]; // [768,768] (out,in)
    float* out = (float*)d_out;                      // [4,256,768]

    __half *hh, *bash;
    cudaGetSymbolAddress((void**)&hh, g_h);
    cudaGetSymbolAddress((void**)&bash, g_bas);

    cvt_kernel<<<(B_ * S_ * H_) / 4 / 256, 256>>>(hidden, hh);
    cvt_kernel<<<(4 * H_ * H_) / 4 / 256, 256>>>(basic, bash);
    t_self_kernel<<<dim3(H_ / 32, H_ / 32), dim3(32, 8)>>>(self_w);
    build_w_kernel<<<B_ * S_, 256>>>(rels, rel_weight);
    gemm_hb_kernel<<<dim3(NTOT / 128, S_ / 128, B_), 256>>>();
    gemm_out_kernel<<<dim3(H_ / 64, S_ / 64, B_), 128>>>(out);
}

// round 6
// speedup vs baseline: 6.8571x; 1.2041x over previous
#include <cuda_runtime.h>
#include <cuda_fp16.h>
#include <cstdint>

#define B_   4
#define S_   256
#define H_   768
#define NTOT 3840   // 5*768 : 4 basis slots + self slot
#define KW   1024   // 4*256 : step-2 K (4 c-blocks of 256)

// ---------------- static device scratch -------------------------------------
__device__ __align__(256) __half g_h[B_ * S_ * H_];      // hidden fp16
__device__ __align__(256) __half g_bas[4 * H_ * H_];     // basic fp16 [c][h][o]
__device__ __align__(256) __half g_self[H_ * H_];        // selfw^T fp16 [h][o]
__device__ __align__(256) __half g_W[B_ * S_ * KW];      // W [b][i][c*256+j]
__device__ __align__(256) __half g_hb[B_ * S_ * NTOT];   // hb [b][s][n]
__device__ __align__(256) int    g_relsT[B_ * S_ * S_];  // rels transposed

// ---------------- helpers ---------------------------------------------------
__device__ __forceinline__ uint32_t s2u(const void* p) {
    uint32_t a;
    asm("{ .reg .u64 t; cvta.to.shared.u64 t, %1; cvt.u32.u64 %0, t; }"
        : "=r"(a) : "l"(p));
    return a;
}
__device__ __forceinline__ void cp16(uint32_t dst, const void* src) {
    asm volatile("cp.async.cg.shared.global [%0], [%1], 16;"
                 :: "r"(dst), "l"(src) : "memory");
}
__device__ __forceinline__ void ldsm4(uint32_t* r, uint32_t addr) {
    asm volatile("ldmatrix.sync.aligned.m8n8.x4.shared.b16 {%0,%1,%2,%3}, [%4];"
                 : "=r"(r[0]), "=r"(r[1]), "=r"(r[2]), "=r"(r[3]) : "r"(addr));
}
__device__ __forceinline__ void ldsm4t(uint32_t* r, uint32_t addr) {
    asm volatile("ldmatrix.sync.aligned.m8n8.x4.trans.shared.b16 {%0,%1,%2,%3}, [%4];"
                 : "=r"(r[0]), "=r"(r[1]), "=r"(r[2]), "=r"(r[3]) : "r"(addr));
}
__device__ __forceinline__ void mma_f16(float* d, const uint32_t* a,
                                        uint32_t b0, uint32_t b1) {
    asm volatile("mma.sync.aligned.m16n8k16.row.col.f32.f16.f16.f32 "
                 "{%0,%1,%2,%3}, {%4,%5,%6,%7}, {%8,%9}, {%0,%1,%2,%3};"
                 : "+f"(d[0]), "+f"(d[1]), "+f"(d[2]), "+f"(d[3])
                 : "r"(a[0]), "r"(a[1]), "r"(a[2]), "r"(a[3]), "r"(b0), "r"(b1));
}

// ---------------- SMEM layout ------------------------------------------------
// A: rows of 64B (32 halves, one 32-K chunk), pitch 80 -> ldsm banks 20r mod 32
//    conflict-free over 8 rows. B: k-rows of NCOLS*2 B + 16B pad; pitch/4*k mod
//    32 = 4k pattern for 272(128n)/144(64n): conflict-free trans ldsm.
#define A_PITCH 80

// A tile: MROWS x 32 halves. B tile: 32 x NCOLS halves. One commit per call.
template<int MROWS, int NCOLS, int BP, int NTH>
__device__ __forceinline__ void issue_chunk32(
    const __half* __restrict__ A, int lda,
    const __half* __restrict__ Bm, int ldb,
    uint32_t a_s, uint32_t b_s, int t)
{
    #pragma unroll
    for (int u = 0; u < MROWS * 4 / NTH; u++) {
        const int id = t + NTH * u;
        const int r = id >> 2, seg = id & 3;
        cp16(a_s + r * A_PITCH + seg * 16, A + (size_t)r * lda + seg * 8);
    }
    #pragma unroll
    for (int u = 0; u < 32 * (NCOLS / 8) / NTH; u++) {
        const int id = t + NTH * u;
        const int k = id / (NCOLS / 8), q = id % (NCOLS / 8);
        cp16(b_s + k * BP + q * 16, Bm + (size_t)k * ldb + q * 8);
    }
    asm volatile("cp.async.commit_group;" ::: "memory");
}

// One 16-K sub-chunk. Warp tile 32 x (NG*16).
template<int BP, int NG>
__device__ __forceinline__ void compute_sub(uint32_t a_s, uint32_t b_s,
                                            float acc[2][NG * 2][4],
                                            int lane, int wm, int wn)
{
    const int arow = wm * 32 + (lane & 15);
    const uint32_t abase = a_s + (uint32_t)arow * A_PITCH + (uint32_t)(lane >> 4) * 16;
    uint32_t ah[2][4], bh[NG][4];
    ldsm4(ah[0], abase);
    ldsm4(ah[1], abase + 16 * A_PITCH);
    const int krow = (lane & 7) | ((lane >> 1) & 8);
    const int noff = (lane & 8) ? 16 : 0;
    #pragma unroll
    for (int g = 0; g < NG; g++)
        ldsm4t(bh[g], b_s + (uint32_t)krow * BP + (uint32_t)(wn * (NG * 32) + g * 32) + noff);
    #pragma unroll
    for (int mt = 0; mt < 2; mt++)
        #pragma unroll
        for (int g = 0; g < NG; g++)
            #pragma unroll
            for (int s = 0; s < 2; s++)
                mma_f16(acc[mt][g * 2 + s], ah[mt], bh[g][s], bh[g][s + 2]);
}

// ---------------------------------------------------------------------------
// Prep kernels
// ---------------------------------------------------------------------------
__global__ void cvt_kernel(const float* __restrict__ src, __half* __restrict__ dst) {
    const int i = blockIdx.x * blockDim.x + threadIdx.x;
    float4 v = reinterpret_cast<const float4*>(src)[i];
    reinterpret_cast<__half2*>(dst)[i * 2]     = __floats2half2_rn(v.x, v.y);
    reinterpret_cast<__half2*>(dst)[i * 2 + 1] = __floats2half2_rn(v.z, v.w);
}

__global__ void t_self_kernel(const float* __restrict__ sw) {
    __shared__ float tile[32][33];
    const int h0 = blockIdx.x * 32, o0 = blockIdx.y * 32;
    const int tx = threadIdx.x, ty = threadIdx.y;
    #pragma unroll
    for (int r = 0; r < 4; r++)
        tile[ty + 8 * r][tx] = sw[(size_t)(o0 + ty + 8 * r) * H_ + h0 + tx];
    __syncthreads();
    #pragma unroll
    for (int r = 0; r < 4; r++)
        g_self[(size_t)(h0 + ty + 8 * r) * H_ + o0 + tx] = __float2half(tile[tx][ty + 8 * r]);
}

// Coalesced 32x32 tiled transpose of rels.
__global__ void t_rels_kernel(const int* __restrict__ rels) {
    __shared__ int tile[32][33];
    const int b = blockIdx.z;
    const int j0 = blockIdx.x * 32, i0 = blockIdx.y * 32;
    const int tx = threadIdx.x, ty = threadIdx.y;
    #pragma unroll
    for (int r = 0; r < 4; r++)
        tile[ty + 8 * r][tx] = rels[((size_t)b * S_ + i0 + ty + 8 * r) * S_ + j0 + tx];
    __syncthreads();
    #pragma unroll
    for (int r = 0; r < 4; r++)
        g_relsT[((size_t)b * S_ + j0 + ty + 8 * r) * S_ + i0 + tx] = tile[tx][ty + 8 * r];
}

// ---------------------------------------------------------------------------
// build_w: histogram + W[b][i][c*256+j] fp16. All reads coalesced (uses relsT).
// ---------------------------------------------------------------------------
__global__ void build_w_kernel(const int* __restrict__ rels,
                               const float* __restrict__ rel_weight) {
    const int bi = blockIdx.x;
    const int b = bi >> 8;
    const int i = bi & 255;
    const int t = threadIdx.x;

    __shared__ int   cf[32], cr[32];
    __shared__ float inv_f[32], inv_r[32];
    __shared__ float rw[64 * 4];

    if (t < 32) { cf[t] = 0; cr[t] = 0; }
    rw[t] = rel_weight[t];
    __syncthreads();

    const int lf = rels[(b * S_ + i) * S_ + t];
    const int lr = g_relsT[(b * S_ + i) * S_ + t];
    if (lf > 0) atomicAdd(&cf[lf], 1);
    if (lr > 0) atomicAdd(&cr[lr], 1);
    __syncthreads();

    if (t < 32) {
        inv_f[t] = 1.0f / (float)(cf[t] > 0 ? cf[t] : 1);
        inv_r[t] = 1.0f / (float)(cr[t] > 0 ? cr[t] : 1);
    }
    __syncthreads();

    float w[4] = {0.f, 0.f, 0.f, 0.f};
    if (lf > 0) {
        const float s = inv_f[lf];
        #pragma unroll
        for (int c = 0; c < 4; c++) w[c] += rw[lf * 4 + c] * s;
    }
    if (lr > 0) {
        const float s = inv_r[lr];
        #pragma unroll
        for (int c = 0; c < 4; c++) w[c] += rw[(lr + 32) * 4 + c] * s;
    }
    #pragma unroll
    for (int c = 0; c < 4; c++)
        g_W[((size_t)(b * S_ + i)) * KW + c * 256 + t] = __float2half(w[c]);
}

// ---------------------------------------------------------------------------
// GEMM-HB: hb[b] (256x3840) = hidden[b] (256x768) @ [basic|selfT] (768x3840)
// grid (30, 2, 4) = 240 CTAs, 256 thr, CTA 128x128, warp 32x64.
// 3-stage cp.async, K-chunk 32 (NC=24), dynamic smem 56832 B.
// ---------------------------------------------------------------------------
#define HB_BP   272
#define HB_ABUF (128 * A_PITCH)                // 10240
#define HB_BBUF (32 * HB_BP)                   // 8704
#define HB_STG  (HB_ABUF + HB_BBUF)            // 18944
#define HB_SMEM (3 * HB_STG)                   // 56832

__global__ __launch_bounds__(256, 2) void gemm_hb_kernel() {
    extern __shared__ __align__(128) char sm[];
    const int n0 = blockIdx.x * 128;     // never straddles a 768-slot
    const int m0 = blockIdx.y * 128;
    const int b  = blockIdx.z;
    const int cslot = n0 / 768;
    const int o0 = n0 - cslot * 768;

    const __half* A  = g_h + ((size_t)(b * S_ + m0)) * H_;
    const __half* Bm = (cslot < 4) ? g_bas + (size_t)cslot * H_ * H_ + o0
                                   : g_self + o0;

    const int t = threadIdx.x, lane = t & 31, wid = t >> 5;
    const int wm = wid & 3, wn = wid >> 2;
    const uint32_t smb = s2u(sm);

    float acc[2][8][4] = {};
    const int NC = 24;
    issue_chunk32<128, 128, HB_BP, 256>(A, H_, Bm, H_, smb, smb + HB_ABUF, t);
    issue_chunk32<128, 128, HB_BP, 256>(A + 32, H_, Bm + (size_t)32 * H_, H_,
                                        smb + HB_STG, smb + HB_STG + HB_ABUF, t);
    for (int c = 0; c < NC; c++) {
        asm volatile("cp.async.wait_group 1;" ::: "memory");
        __syncthreads();
        const uint32_t st = smb + (uint32_t)(c % 3) * HB_STG;
        compute_sub<HB_BP, 4>(st, st + HB_ABUF, acc, lane, wm, wn);
        compute_sub<HB_BP, 4>(st + 32, st + HB_ABUF + 16 * HB_BP, acc, lane, wm, wn);
        if (c + 2 < NC) {
            const int k0 = (c + 2) * 32;
            const uint32_t sn = smb + (uint32_t)((c + 2) % 3) * HB_STG;
            issue_chunk32<128, 128, HB_BP, 256>(A + k0, H_, Bm + (size_t)k0 * H_, H_,
                                                sn, sn + HB_ABUF, t);
        } else {
            asm volatile("cp.async.commit_group;" ::: "memory");
        }
    }

    #pragma unroll
    for (int mt = 0; mt < 2; mt++)
        #pragma unroll
        for (int nt = 0; nt < 8; nt++) {
            const int row = m0 + wm * 32 + mt * 16 + (lane >> 2);
            const int col = n0 + wn * 64 + nt * 8 + (lane & 3) * 2;
            *reinterpret_cast<__half2*>(g_hb + (size_t)(b * S_ + row) * NTOT + col) =
                __floats2half2_rn(acc[mt][nt][0], acc[mt][nt][1]);
            *reinterpret_cast<__half2*>(g_hb + (size_t)(b * S_ + row + 8) * NTOT + col) =
                __floats2half2_rn(acc[mt][nt][2], acc[mt][nt][3]);
        }
}

// ---------------------------------------------------------------------------
// GEMM-OUT: out[b] (256x768) = W[b] (256x1024) @ hb_stack (1024x768) + self
// grid (12, 4, 4) = 192 CTAs, 128 thr, CTA 64x64, warp 32x32.
// 3-stage, K-chunk 32 (NC=32), static smem 29184 B.
// ---------------------------------------------------------------------------
#define OUT_BP   144
#define OUT_ABUF (64 * A_PITCH)                // 5120
#define OUT_BBUF (32 * OUT_BP)                 // 4608
#define OUT_STG  (OUT_ABUF + OUT_BBUF)         // 9728

__global__ __launch_bounds__(128, 3) void gemm_out_kernel(float* __restrict__ out) {
    __shared__ __align__(128) char sm[3 * OUT_STG];
    const int n0 = blockIdx.x * 64;
    const int m0 = blockIdx.y * 64;
    const int b  = blockIdx.z;

    const __half* A  = g_W + ((size_t)(b * S_ + m0)) * KW;
    const __half* hb = g_hb + (size_t)b * S_ * NTOT + n0;

    const int t = threadIdx.x, lane = t & 31, wid = t >> 5;
    const int wm = wid & 1, wn = wid >> 1;
    const uint32_t smb = s2u(sm);

    float acc[2][4][4] = {};
    const int NC = 32;
    // B row k=(c*256+j) -> hb[b][j][cb*768+n]; chunk of 32 never straddles.
    issue_chunk32<64, 64, OUT_BP, 128>(A, KW, hb, NTOT, smb, smb + OUT_ABUF, t);
    {
        const size_t boff = (size_t)32 * NTOT;
        issue_chunk32<64, 64, OUT_BP, 128>(A + 32, KW, hb + boff, NTOT,
                                           smb + OUT_STG, smb + OUT_STG + OUT_ABUF, t);
    }
    for (int c = 0; c < NC; c++) {
        asm volatile("cp.async.wait_group 1;" ::: "memory");
        __syncthreads();
        const uint32_t st = smb + (uint32_t)(c % 3) * OUT_STG;
        compute_sub<OUT_BP, 2>(st, st + OUT_ABUF, acc, lane, wm, wn);
        compute_sub<OUT_BP, 2>(st + 32, st + OUT_ABUF + 16 * OUT_BP, acc, lane, wm, wn);
        if (c + 2 < NC) {
            const int k0 = (c + 2) * 32;
            const size_t boff = (size_t)(k0 >> 8) * 768 + (size_t)(k0 & 255) * NTOT;
            const uint32_t sn = smb + (uint32_t)((c + 2) % 3) * OUT_STG;
            issue_chunk32<64, 64, OUT_BP, 128>(A + k0, KW, hb + boff, NTOT,
                                               sn, sn + OUT_ABUF, t);
        } else {
            asm volatile("cp.async.commit_group;" ::: "memory");
        }
    }

    // epilogue: add self slot (hb[:, 3072+n]) and store fp32
    #pragma unroll
    for (int mt = 0; mt < 2; mt++)
        #pragma unroll
        for (int nt = 0; nt < 4; nt++) {
            const int row = m0 + wm * 32 + mt * 16 + (lane >> 2);
            const int col = n0 + wn * 32 + nt * 8 + (lane & 3) * 2;
            #pragma unroll
            for (int hf = 0; hf < 2; hf++) {
                const int r = row + hf * 8;
                __half2 sh = *reinterpret_cast<const __half2*>(
                    g_hb + (size_t)(b * S_ + r) * NTOT + 3072 + col);
                float2 v;
                v.x = acc[mt][nt][hf * 2 + 0] + __half2float(sh.x);
                v.y = acc[mt][nt][hf * 2 + 1] + __half2float(sh.y);
                *reinterpret_cast<float2*>(out + (size_t)(b * S_ + r) * H_ + col) = v;
            }
        }
}

// ---------------------------------------------------------------------------
extern "C" void kernel_launch(void* const* d_in, const int* in_sizes, int n_in,
                              void* d_out, int out_size) {
    const float* hidden     = (const float*)d_in[0]; // [4,256,768]
    const int*   rels       = (const int*)  d_in[1]; // [4,256,256]
    const float* basic      = (const float*)d_in[2]; // [4,768,768]
    const float* rel_weight = (const float*)d_in[3]; // [64,4]
    const float* self_w     = (const float*)d_in[4]; // [768,768] (out,in)
    float* out = (float*)d_out;                      // [4,256,768]

    __half *hh, *bash;
    cudaGetSymbolAddress((void**)&hh, g_h);
    cudaGetSymbolAddress((void**)&bash, g_bas);
    cudaFuncSetAttribute(gemm_hb_kernel,
                         cudaFuncAttributeMaxDynamicSharedMemorySize, HB_SMEM);

    t_rels_kernel<<<dim3(8, 8, B_), dim3(32, 8)>>>(rels);
    cvt_kernel<<<(B_ * S_ * H_) / 4 / 256, 256>>>(hidden, hh);
    cvt_kernel<<<(4 * H_ * H_) / 4 / 256, 256>>>(basic, bash);
    t_self_kernel<<<dim3(H_ / 32, H_ / 32), dim3(32, 8)>>>(self_w);
    build_w_kernel<<<B_ * S_, 256>>>(rels, rel_weight);
    gemm_hb_kernel<<<dim3(NTOT / 128, S_ / 128, B_), 256, HB_SMEM>>>();
    gemm_out_kernel<<<dim3(H_ / 64, S_ / 64, B_), 128>>>(out);
}